// round 1
// baseline (speedup 1.0000x reference)
#include <cuda_runtime.h>

// YOLOv1 loss: pred [4096,14,14,30] fp32, target same, output scalar fp32.
// S=14, B=2 boxes, C=20 classes, N=30 channels/cell.
// HBM-bound streaming reduction: stage 128-cell tiles through shared memory
// with coalesced float4 loads, compute per-cell loss, hierarchical reduce.

#define S_GRID   14
#define NBATCH   4096
#define NCH      30
#define NCELLS   (NBATCH * S_GRID * S_GRID)   // 802816
#define TILE_C   128                          // cells per tile
#define NTILES   (NCELLS / TILE_C)            // 6272 (exact)
#define BLOCK    128
#define TILE_F4  ((TILE_C * NCH) / 4)         // 960 float4 per array per tile
#define GRID_MAX 1184                         // 8 * 148 SMs

__global__ void yolo_zero_out(float* out) {
    if (threadIdx.x == 0) out[0] = 0.0f;
}

__global__ __launch_bounds__(BLOCK)
void yolo_loss_kernel(const float4* __restrict__ pred4,
                      const float4* __restrict__ tgt4,
                      float* __restrict__ out)
{
    __shared__ float sp[TILE_C * NCH];   // 15360 B
    __shared__ float st[TILE_C * NCH];   // 15360 B
    __shared__ float wsum[BLOCK / 32];

    const float invS = 1.0f / 14.0f;
    float acc = 0.0f;

    for (int tile = blockIdx.x; tile < NTILES; tile += gridDim.x) {
        const int base4 = tile * TILE_F4;
        __syncthreads();   // protect smem from previous tile's readers
        for (int i = threadIdx.x; i < TILE_F4; i += BLOCK) {
            ((float4*)sp)[i] = __ldg(pred4 + base4 + i);
            ((float4*)st)[i] = __ldg(tgt4  + base4 + i);
        }
        __syncthreads();

        const float* p = sp + threadIdx.x * NCH;
        const float* t = st + threadIdx.x * NCH;

        // target box 0 (boxes are tiled identical in target)
        const float t0x = t[0], t0y = t[1], t0w = t[2], t0h = t[3];
        const float tobj = t[4];
        const float of = (tobj > 0.0f) ? 1.0f : 0.0f;

        const float tcx = t0x * invS, tcy = t0y * invS;
        const float thw = 0.5f * t0w, thh = 0.5f * t0h;
        const float tx0 = tcx - thw, tx1 = tcx + thw;
        const float ty0 = tcy - thh, ty1 = tcy + thh;
        const float area_t = t0w * t0h;

        float iou[2], px[2], py[2], pw[2], ph[2], pc[2];
        #pragma unroll
        for (int b = 0; b < 2; b++) {
            px[b] = p[5*b + 0]; py[b] = p[5*b + 1];
            pw[b] = p[5*b + 2]; ph[b] = p[5*b + 3];
            pc[b] = p[5*b + 4];
            const float pcx = px[b] * invS, pcy = py[b] * invS;
            const float phw = 0.5f * pw[b], phh = 0.5f * ph[b];
            const float px0 = pcx - phw, px1 = pcx + phw;
            const float py0 = pcy - phh, py1 = pcy + phh;
            const float ltx = fmaxf(px0, tx0), lty = fmaxf(py0, ty0);
            const float rbx = fminf(px1, tx1), rby = fminf(py1, ty1);
            const float wi = fmaxf(rbx - ltx, 0.0f);
            const float hi = fmaxf(rby - lty, 0.0f);
            const float inter = wi * hi;
            const float area_p = pw[b] * ph[b];
            iou[b] = inter / (area_p + area_t - inter);
        }

        // argmax over 2 boxes; ties -> box 0 (matches jnp.argmax first-max)
        const int b = (iou[1] > iou[0]) ? 1 : 0;
        const float max_iou = fmaxf(iou[0], iou[1]);

        const float dx = px[b] - t0x, dy = py[b] - t0y;
        const float lxy = dx*dx + dy*dy;
        const float dw = sqrtf(pw[b]) - sqrtf(t0w);
        const float dh = sqrtf(ph[b]) - sqrtf(t0h);
        const float lwh = dw*dw + dh*dh;
        const float dob = pc[b] - max_iou;
        const float lobj = dob * dob;
        const float lno = pc[0]*pc[0] + pc[1]*pc[1];   // target conf = 0 when no obj

        float lcls = 0.0f;
        #pragma unroll
        for (int c = 0; c < 20; c++) {
            const float d = p[10 + c] - t[10 + c];
            lcls += d * d;
        }

        acc += of * (5.0f * (lxy + lwh) + lobj + lcls)
             + (1.0f - of) * (0.5f * lno);
    }

    acc *= (1.0f / (float)NBATCH);

    // warp reduce
    #pragma unroll
    for (int o = 16; o > 0; o >>= 1)
        acc += __shfl_down_sync(0xffffffffu, acc, o);
    if ((threadIdx.x & 31) == 0) wsum[threadIdx.x >> 5] = acc;
    __syncthreads();
    if (threadIdx.x == 0) {
        float s = 0.0f;
        #pragma unroll
        for (int w = 0; w < BLOCK / 32; w++) s += wsum[w];
        atomicAdd(out, s);
    }
}

extern "C" void kernel_launch(void* const* d_in, const int* in_sizes, int n_in,
                              void* d_out, int out_size)
{
    const float4* pred4 = (const float4*)d_in[0];
    const float4* tgt4  = (const float4*)d_in[1];
    float* out = (float*)d_out;

    yolo_zero_out<<<1, 32>>>(out);
    int grid = NTILES < GRID_MAX ? NTILES : GRID_MAX;
    yolo_loss_kernel<<<grid, BLOCK>>>(pred4, tgt4, out);
}

// round 3
// speedup vs baseline: 1.3878x; 1.3878x over previous
#include <cuda_runtime.h>
#include <cstdint>

// YOLOv1 loss: pred [4096,14,14,30] fp32, target same, output scalar fp32.
// HBM-bound streaming reduction. R3 = R2 + missing <cstdint>:
// stage tiles via cp.async.cg (LDGSTS) to decouple memory-level parallelism
// from register count; 15 fire-and-forget 16B copies per thread per tile.

#define S_GRID   14
#define NBATCH   4096
#define NCH      30
#define NCELLS   (NBATCH * S_GRID * S_GRID)   // 802816
#define TILE_C   128                          // cells per tile
#define NTILES   (NCELLS / TILE_C)            // 6272 (exact)
#define BLOCK    128
#define TILE_F4  ((TILE_C * NCH) / 4)         // 960 float4 per array per tile
#define CP_PER_T ((2 * TILE_F4) / BLOCK)      // 15 cp.async per thread
#define GRID_MAX 1184                         // 8 * 148 SMs

__global__ void yolo_zero_out(float* out) {
    if (threadIdx.x == 0) out[0] = 0.0f;
}

__device__ __forceinline__ void cp_async16(uint32_t smem_dst, const void* gsrc) {
    asm volatile("cp.async.cg.shared.global [%0], [%1], 16;\n"
                 :: "r"(smem_dst), "l"(gsrc));
}

__global__ __launch_bounds__(BLOCK)
void yolo_loss_kernel(const float4* __restrict__ pred4,
                      const float4* __restrict__ tgt4,
                      float* __restrict__ out)
{
    __shared__ float sp[TILE_C * NCH];   // 15360 B
    __shared__ float st[TILE_C * NCH];   // 15360 B
    __shared__ float wsum[BLOCK / 32];

    const uint32_t sp_base = (uint32_t)__cvta_generic_to_shared(sp);
    const uint32_t st_base = (uint32_t)__cvta_generic_to_shared(st);

    const float invS = 1.0f / 14.0f;
    float acc = 0.0f;

    for (int tile = blockIdx.x; tile < NTILES; tile += gridDim.x) {
        const int base4 = tile * TILE_F4;
        __syncthreads();   // protect smem from previous tile's readers

        // 2*TILE_F4 = 1920 16B copies; 15 per thread, constant trip count.
        // j in [0,960) -> sp from pred, j in [960,1920) -> st from target.
        #pragma unroll
        for (int k = 0; k < CP_PER_T; k++) {
            const int j = threadIdx.x + k * BLOCK;
            if (j < TILE_F4) {
                cp_async16(sp_base + (uint32_t)j * 16u, pred4 + base4 + j);
            } else {
                const int i = j - TILE_F4;
                cp_async16(st_base + (uint32_t)i * 16u, tgt4 + base4 + i);
            }
        }
        asm volatile("cp.async.commit_group;\n" ::: "memory");
        asm volatile("cp.async.wait_group 0;\n" ::: "memory");
        __syncthreads();

        const float* p = sp + threadIdx.x * NCH;
        const float* t = st + threadIdx.x * NCH;

        // target box 0 (boxes are tiled identical in target)
        const float t0x = t[0], t0y = t[1], t0w = t[2], t0h = t[3];
        const float tobj = t[4];
        const float of = (tobj > 0.0f) ? 1.0f : 0.0f;

        const float tcx = t0x * invS, tcy = t0y * invS;
        const float thw = 0.5f * t0w, thh = 0.5f * t0h;
        const float tx0 = tcx - thw, tx1 = tcx + thw;
        const float ty0 = tcy - thh, ty1 = tcy + thh;
        const float area_t = t0w * t0h;

        float iou[2], px[2], py[2], pw[2], ph[2], pc[2];
        #pragma unroll
        for (int b = 0; b < 2; b++) {
            px[b] = p[5*b + 0]; py[b] = p[5*b + 1];
            pw[b] = p[5*b + 2]; ph[b] = p[5*b + 3];
            pc[b] = p[5*b + 4];
            const float pcx = px[b] * invS, pcy = py[b] * invS;
            const float phw = 0.5f * pw[b], phh = 0.5f * ph[b];
            const float px0 = pcx - phw, px1 = pcx + phw;
            const float py0 = pcy - phh, py1 = pcy + phh;
            const float ltx = fmaxf(px0, tx0), lty = fmaxf(py0, ty0);
            const float rbx = fminf(px1, tx1), rby = fminf(py1, ty1);
            const float wi = fmaxf(rbx - ltx, 0.0f);
            const float hi = fmaxf(rby - lty, 0.0f);
            const float inter = wi * hi;
            const float area_p = pw[b] * ph[b];
            iou[b] = inter / (area_p + area_t - inter);
        }

        // argmax over 2 boxes; ties -> box 0 (matches jnp.argmax first-max)
        const int b = (iou[1] > iou[0]) ? 1 : 0;
        const float max_iou = fmaxf(iou[0], iou[1]);

        const float dx = px[b] - t0x, dy = py[b] - t0y;
        const float lxy = dx*dx + dy*dy;
        const float dw = sqrtf(pw[b]) - sqrtf(t0w);
        const float dh = sqrtf(ph[b]) - sqrtf(t0h);
        const float lwh = dw*dw + dh*dh;
        const float dob = pc[b] - max_iou;
        const float lobj = dob * dob;
        const float lno = pc[0]*pc[0] + pc[1]*pc[1];   // target conf = 0 when no obj

        float lcls = 0.0f;
        #pragma unroll
        for (int c = 0; c < 20; c++) {
            const float d = p[10 + c] - t[10 + c];
            lcls += d * d;
        }

        acc += of * (5.0f * (lxy + lwh) + lobj + lcls)
             + (1.0f - of) * (0.5f * lno);
    }

    acc *= (1.0f / (float)NBATCH);

    // warp reduce
    #pragma unroll
    for (int o = 16; o > 0; o >>= 1)
        acc += __shfl_down_sync(0xffffffffu, acc, o);
    if ((threadIdx.x & 31) == 0) wsum[threadIdx.x >> 5] = acc;
    __syncthreads();
    if (threadIdx.x == 0) {
        float s = 0.0f;
        #pragma unroll
        for (int w = 0; w < BLOCK / 32; w++) s += wsum[w];
        atomicAdd(out, s);
    }
}

extern "C" void kernel_launch(void* const* d_in, const int* in_sizes, int n_in,
                              void* d_out, int out_size)
{
    const float4* pred4 = (const float4*)d_in[0];
    const float4* tgt4  = (const float4*)d_in[1];
    float* out = (float*)d_out;

    yolo_zero_out<<<1, 32>>>(out);
    int grid = NTILES < GRID_MAX ? NTILES : GRID_MAX;
    yolo_loss_kernel<<<grid, BLOCK>>>(pred4, tgt4, out);
}